// round 12
// baseline (speedup 1.0000x reference)
#include <cuda_runtime.h>
#include <cuda_bf16.h>
#include <cuda_fp16.h>
#include <cstdint>

#define NN   1024
#define NN2  (NN * NN)
#define BD   64
#define NB   128
#define ROWB 144         // 128B k-data (BK=64) + 16B pad

// ============================================================================
// Device global scratch (allocation-free rule)
// ============================================================================
__device__ __align__(16) __half g_Sh[NN2];                         // S^T, fp16
__device__ __align__(16) __half g_Ta_h[NN2], g_Ta_l[NN2];
__device__ __align__(16) __half g_Tb_h[NN2], g_Tb_l[NN2];
__device__ __align__(16) __half g_Xh[(size_t)NB * BD * NN];        // X^T, fp16
__device__ __align__(16) float  g_part[4][NN2];
__device__ unsigned g_genArr[8];   // band barrier generation (monotonic)
__device__ unsigned g_cntArr[8];   // band barrier arrival count (returns to 0)

// ============================================================================
// PTX helpers (baseline sm_80-class, legal under compute_103)
// ============================================================================
__device__ __forceinline__ uint32_t smem_to_u32(const void* p) {
    uint32_t a;
    asm("{ .reg .u64 t; cvta.to.shared.u64 t, %1; cvt.u32.u64 %0, t; }"
        : "=r"(a) : "l"(p));
    return a;
}
__device__ __forceinline__ void cp16(uint32_t s, const void* g) {
    asm volatile("cp.async.cg.shared.global [%0], [%1], 16;" :: "r"(s), "l"(g));
}
#define CP_COMMIT() asm volatile("cp.async.commit_group;" ::: "memory")
#define CP_WAIT(n)  asm volatile("cp.async.wait_group %0;" :: "n"(n) : "memory")

__device__ __forceinline__ void ldsm4(uint32_t& r0, uint32_t& r1,
                                      uint32_t& r2, uint32_t& r3, uint32_t a) {
    asm volatile("ldmatrix.sync.aligned.m8n8.x4.shared.b16 {%0,%1,%2,%3}, [%4];"
                 : "=r"(r0), "=r"(r1), "=r"(r2), "=r"(r3) : "r"(a));
}
__device__ __forceinline__ void mma_f16(float* c, const uint32_t* a,
                                        uint32_t b0, uint32_t b1) {
    asm volatile(
        "mma.sync.aligned.m16n8k16.row.col.f32.f16.f16.f32 "
        "{%0,%1,%2,%3}, {%4,%5,%6,%7}, {%8,%9}, {%0,%1,%2,%3};"
        : "+f"(c[0]), "+f"(c[1]), "+f"(c[2]), "+f"(c[3])
        : "r"(a[0]), "r"(a[1]), "r"(a[2]), "r"(a[3]), "r"(b0), "r"(b1));
}

__device__ __forceinline__ void split_f16(float v, __half& h, __half& l) {
    h = __float2half(v);
    l = __float2half(v - __half2float(h));
}

// Band-local grid barrier: 32 CTAs per band, generation-based.
// Safe across graph replays: g_cntArr returns to 0, g_genArr is monotonic.
__device__ __forceinline__ void band_sync(int band) {
    __threadfence();           // make this CTA's global writes visible
    __syncthreads();
    if (threadIdx.x == 0) {
        volatile unsigned* gen = (volatile unsigned*)&g_genArr[band];
        unsigned my = *gen;
        if (atomicAdd(&g_cntArr[band], 1u) == 31u) {
            g_cntArr[band] = 0;
            __threadfence();
            *gen = my + 1;
        } else {
            while (*gen == my) { }
            __threadfence();   // acquire
        }
    }
    __syncthreads();
}

// ============================================================================
// Converts
// ============================================================================
// Sh[n][k] = fp16(S[k][n])
__global__ __launch_bounds__(256) void convert_St(const float* __restrict__ S) {
    __shared__ float tile[64][65];
    int k0 = blockIdx.x * 64, n0 = blockIdx.y * 64;
    for (int idx = threadIdx.x; idx < 64 * 64; idx += 256) {
        int r = idx >> 6, c = idx & 63;
        tile[r][c] = S[(size_t)(k0 + r) * NN + n0 + c];
    }
    __syncthreads();
    for (int idx = threadIdx.x; idx < 64 * 64; idx += 256) {
        int r = idx >> 6, c = idx & 63;
        g_Sh[(size_t)(n0 + r) * NN + k0 + c] = __float2half(tile[c][r]);
    }
}
// Xh[b][d][k] = fp16(X[b][k][d])
__global__ __launch_bounds__(256) void convert_X(const float* __restrict__ X) {
    __shared__ float tile[64][65];
    int k0 = blockIdx.x * 64, b = blockIdx.y;
    for (int idx = threadIdx.x; idx < 64 * 64; idx += 256) {
        int r = idx >> 6, c = idx & 63;
        tile[r][c] = X[((size_t)b * NN + k0 + r) * BD + c];
    }
    __syncthreads();
    for (int idx = threadIdx.x; idx < 64 * 64; idx += 256) {
        int r = idx >> 6, c = idx & 63;
        g_Xh[((size_t)b * BD + r) * NN + k0 + c] = __float2half(tile[c][r]);
    }
}

// ============================================================================
// GEMM core macros: tile 128x128, 256 thr (warps 2Mx4N, warp tile 64x32),
// BK=64, 3-stage cp.async ring. Stage = 256 rows x 144B = 36864 B.
// ============================================================================
#define STG_BYTES (256 * ROWB)
#define OP_SMEM   (3 * STG_BYTES)

#define LOAD_STAGE(Ap, Bp, k, slot)                                           \
    do {                                                                      \
        const uint32_t _base = sbase + (slot) * STG_BYTES;                    \
        _Pragma("unroll")                                                     \
        for (int _i = 0; _i < 8; ++_i) {                                      \
            int _idx = tid + _i * 256;                                        \
            int _r = _idx >> 3, _c = _idx & 7;                                \
            const void* _src = (_r < 128)                                     \
                ? (const void*)((Ap) + (size_t)(row0 + _r) * NN + (k) + _c * 8)   \
                : (const void*)((Bp) + (size_t)(col0 + _r - 128) * NN + (k) + _c * 8); \
            cp16(_base + _r * ROWB + _c * 16, _src);                          \
        }                                                                     \
        CP_COMMIT();                                                          \
    } while (0)

#define LDS_A(a, k16, sA)                                                     \
    _Pragma("unroll")                                                         \
    for (int _mt = 0; _mt < 4; ++_mt)                                         \
        ldsm4((a)[_mt][0], (a)[_mt][1], (a)[_mt][2], (a)[_mt][3],             \
              (sA) + (uint32_t)(wm + _mt * 16 + (lane & 15)) * ROWB           \
                   + (uint32_t)((k16) * 2 + (lane >> 4)) * 16)

#define LDS_B(b, k16, sB)                                                     \
    _Pragma("unroll")                                                         \
    for (int _p = 0; _p < 2; ++_p)                                            \
        ldsm4((b)[_p][0], (b)[_p][1], (b)[_p][2], (b)[_p][3],                 \
              (sB) + (uint32_t)(wn + _p * 16 + ((lane >> 4) << 3) + (lane & 7)) * ROWB \
                   + (uint32_t)((k16) * 2 + ((lane >> 3) & 1)) * 16)

#define MMA_ALL(acc, a, b)                                                    \
    _Pragma("unroll")                                                         \
    for (int _mt = 0; _mt < 4; ++_mt)                                         \
        _Pragma("unroll")                                                     \
        for (int _nt = 0; _nt < 4; ++_nt)                                     \
            mma_f16((acc)[_mt][_nt], (a)[_mt],                                \
                    (b)[_nt >> 1][(_nt & 1) * 2], (b)[_nt >> 1][(_nt & 1) * 2 + 1])

// ============================================================================
// chain_persistent: the full 7-step Horner chain in one launch.
// 256 CTAs = 8 independent row-bands x (8 col-tiles x 4 K-splits).
// Band y owns T rows [128y, 128y+128): init-convert, 7x (MMA partial ->
// band_sync -> distributed reduce+split -> band_sync). Row-bands never
// interact because (T.S)[rows] depends only on T[rows].
// ============================================================================
__global__ __launch_bounds__(256, 2)
void chain_persistent(const float* __restrict__ weight) {
    extern __shared__ __align__(16) char smem[];
    const int tid  = threadIdx.x;
    const int lane = tid & 31, w = tid >> 5;
    const int wm   = (w >> 2) * 64;
    const int wn   = (w & 3) * 32;
    const int bidx = blockIdx.x;
    const int x    = bidx & 7;          // col tile
    const int z    = (bidx >> 3) & 3;   // K split
    const int y    = bidx >> 5;         // row band
    const int row0 = y * 128;
    const int col0 = x * 128;
    const int kb   = z * 512;
    const int sub  = x + 8 * z;         // 0..31 within band
    const uint32_t sbase = smem_to_u32(smem);

    const size_t sliceBase = (size_t)y * 131072 + (size_t)sub * 4096 + tid * 4;

    // ---- init: Ta = fp16split(W7) over this CTA's band slice ----
    {
        const float* W7 = weight + (size_t)7 * NN2;
        #pragma unroll
        for (int j = 0; j < 4; ++j) {
            size_t i = sliceBase + j * 1024;
            float4 wv = *(const float4*)&W7[i];
            __half h0, l0, h1, l1, h2, l2, h3, l3;
            split_f16(wv.x, h0, l0); split_f16(wv.y, h1, l1);
            split_f16(wv.z, h2, l2); split_f16(wv.w, h3, l3);
            *(__half2*)(g_Ta_h + i)     = __halves2half2(h0, h1);
            *(__half2*)(g_Ta_h + i + 2) = __halves2half2(h2, h3);
            *(__half2*)(g_Ta_l + i)     = __halves2half2(l0, l1);
            *(__half2*)(g_Ta_l + i + 2) = __halves2half2(l2, l3);
        }
    }
    band_sync(y);

    for (int step = 0; step < 7; ++step) {
        const int inSel = step & 1;
        const __half* Ah = inSel ? g_Tb_h : g_Ta_h;
        const __half* Al = inSel ? g_Tb_l : g_Ta_l;

        // ---- MMA partial: g_part[z] tile = (T chunk) @ Sh ----
        auto issue = [&](int s, int slot) {
            const int kk = kb + s * 64;          // 0..2047
            const int k  = kk & 1023;
            const __half* Ap = (kk < 1024) ? Ah : Al;
            LOAD_STAGE(Ap, g_Sh, k, slot);
        };

        float acc[4][4][4] = {};
        issue(0, 0); issue(1, 1);

        for (int s = 0; s < 8; ++s) {
            CP_WAIT(1);
            __syncthreads();
            const uint32_t sA = sbase + (s % 3) * STG_BYTES;
            const uint32_t sB = sA + 128 * ROWB;

            uint32_t a[4][4], b[2][4];
            LDS_A(a, 0, sA); LDS_B(b, 0, sB);
            if (s + 2 < 8) issue(s + 2, (s + 2) % 3); else CP_COMMIT();
            MMA_ALL(acc, a, b);
            #pragma unroll
            for (int k16 = 1; k16 < 4; ++k16) {
                LDS_A(a, k16, sA); LDS_B(b, k16, sB);
                MMA_ALL(acc, a, b);
            }
        }
        CP_WAIT(0);   // drain pipeline before smem reuse next step

        float* P = g_part[z];
        const int g  = lane >> 2;
        const int i2 = (lane & 3) * 2;
        #pragma unroll
        for (int mt = 0; mt < 4; ++mt)
            #pragma unroll
            for (int nt = 0; nt < 4; ++nt) {
                const int m0 = row0 + wm + mt * 16 + g;
                const int n  = col0 + wn + nt * 8 + i2;
                *(float2*)(P + (size_t)m0 * NN + n) =
                    make_float2(acc[mt][nt][0], acc[mt][nt][1]);
                *(float2*)(P + (size_t)(m0 + 8) * NN + n) =
                    make_float2(acc[mt][nt][2], acc[mt][nt][3]);
            }

        band_sync(y);

        // ---- distributed reduce: T_next = fp16split(sum(parts) + Wk) ----
        {
            __half* Oh = inSel ? g_Ta_h : g_Tb_h;
            __half* Ol = inSel ? g_Ta_l : g_Tb_l;
            const float* Wk = weight + (size_t)(6 - step) * NN2;
            #pragma unroll
            for (int j = 0; j < 4; ++j) {
                size_t i = sliceBase + j * 1024;
                float4 p0 = *(const float4*)&g_part[0][i];
                float4 p1 = *(const float4*)&g_part[1][i];
                float4 p2 = *(const float4*)&g_part[2][i];
                float4 p3 = *(const float4*)&g_part[3][i];
                float4 wv = *(const float4*)&Wk[i];
                float v0 = p0.x + p1.x + p2.x + p3.x + wv.x;
                float v1 = p0.y + p1.y + p2.y + p3.y + wv.y;
                float v2 = p0.z + p1.z + p2.z + p3.z + wv.z;
                float v3 = p0.w + p1.w + p2.w + p3.w + wv.w;
                __half h0, l0, h1, l1, h2, l2, h3, l3;
                split_f16(v0, h0, l0); split_f16(v1, h1, l1);
                split_f16(v2, h2, l2); split_f16(v3, h3, l3);
                *(__half2*)(Oh + i)     = __halves2half2(h0, h1);
                *(__half2*)(Oh + i + 2) = __halves2half2(h2, h3);
                *(__half2*)(Ol + i)     = __halves2half2(l0, l1);
                *(__half2*)(Ol + i + 2) = __halves2half2(l2, l3);
            }
        }
        band_sync(y);
    }
}

// ============================================================================
// gemm_final: out = (Th + Tl) @ Xh  — fp16 2-term, Kext = 2048 (32 stages).
// grid (64, 8) = 512 CTAs, 256 threads.  [unchanged from R11]
// ============================================================================
__global__ __launch_bounds__(256, 2)
void gemm_final(float* __restrict__ outp) {
    extern __shared__ __align__(16) char smem[];
    const int tid  = threadIdx.x;
    const int lane = tid & 31, w = tid >> 5;
    const int wm   = (w >> 2) * 64;
    const int wn   = (w & 3) * 32;
    const int row0 = blockIdx.y * 128;
    const int col0 = blockIdx.x * 128;     // global column in [0, 8192)
    const uint32_t sbase = smem_to_u32(smem);

    auto issue = [&](int s, int slot) {
        const int kk = s * 64;
        const int k  = kk & 1023;
        const __half* Ap = (kk < 1024) ? g_Tb_h : g_Tb_l;
        LOAD_STAGE(Ap, g_Xh, k, slot);
    };

    float acc[4][4][4] = {};
    issue(0, 0); issue(1, 1);

    for (int s = 0; s < 32; ++s) {
        CP_WAIT(1);
        __syncthreads();
        const uint32_t sA = sbase + (s % 3) * STG_BYTES;
        const uint32_t sB = sA + 128 * ROWB;

        uint32_t a[4][4], b[2][4];
        LDS_A(a, 0, sA); LDS_B(b, 0, sB);
        if (s + 2 < 32) issue(s + 2, (s + 2) % 3); else CP_COMMIT();
        MMA_ALL(acc, a, b);
        #pragma unroll
        for (int k16 = 1; k16 < 4; ++k16) {
            LDS_A(a, k16, sA); LDS_B(b, k16, sB);
            MMA_ALL(acc, a, b);
        }
    }

    const int g  = lane >> 2;
    const int i2 = (lane & 3) * 2;
    #pragma unroll
    for (int mt = 0; mt < 4; ++mt)
        #pragma unroll
        for (int nt = 0; nt < 4; ++nt) {
            const int m0    = row0 + wm + mt * 16 + g;
            const int ncolg = col0 + wn + nt * 8 + i2;
            const int batch = ncolg >> 6;
            const int d     = ncolg & 63;
            float* o0 = outp + ((size_t)batch * NN + m0) * BD + d;
            float* o1 = outp + ((size_t)batch * NN + m0 + 8) * BD + d;
            *(float2*)o0 = make_float2(acc[mt][nt][0], acc[mt][nt][1]);
            *(float2*)o1 = make_float2(acc[mt][nt][2], acc[mt][nt][3]);
        }
}

// ============================================================================
// Host orchestration:
//   converts -> persistent Horner chain (1 launch) -> final GEMM
// ============================================================================
extern "C" void kernel_launch(void* const* d_in, const int* in_sizes, int n_in,
                              void* d_out, int out_size) {
    const float* nodes  = (const float*)d_in[0];   // [128, 1024, 64]
    const float* weight = (const float*)d_in[1];   // [8, 1024, 1024]
    const float* S      = (const float*)d_in[2];   // [1024, 1024]
    float* out = (float*)d_out;                    // [128, 1024, 64]

    cudaFuncSetAttribute(chain_persistent, cudaFuncAttributeMaxDynamicSharedMemorySize, OP_SMEM);
    cudaFuncSetAttribute(gemm_final,       cudaFuncAttributeMaxDynamicSharedMemorySize, OP_SMEM);

    convert_St<<<dim3(16, 16), 256>>>(S);
    convert_X <<<dim3(16, NB), 256>>>(nodes);

    chain_persistent<<<256, 256, OP_SMEM>>>(weight);   // lands in g_Tb (7 steps)
    gemm_final<<<dim3(64, 8), 256, OP_SMEM>>>(out);
}

// round 13
// speedup vs baseline: 1.3070x; 1.3070x over previous
#include <cuda_runtime.h>
#include <cuda_bf16.h>
#include <cuda_fp16.h>
#include <cstdint>

#define NN   1024
#define NN2  (NN * NN)
#define BD   64
#define NB   128
#define ROWB 144         // 128B k-data (BK=64) + 16B pad

// ============================================================================
// Device global scratch (allocation-free rule).  All-fp16 pipeline:
//   T carried as fp16 hi/lo pair (22-bit), S and X as fp16 hi only.
// ============================================================================
__device__ __align__(16) __half g_Sh[NN2];                         // S^T, fp16
__device__ __align__(16) __half g_Ta_h[NN2], g_Ta_l[NN2];
__device__ __align__(16) __half g_Tb_h[NN2], g_Tb_l[NN2];
__device__ __align__(16) __half g_Xh[(size_t)NB * BD * NN];        // X^T, fp16
__device__ __align__(16) float  g_part[4][NN2];

// ============================================================================
// PTX helpers (baseline sm_80-class, legal under compute_103)
// ============================================================================
__device__ __forceinline__ uint32_t smem_to_u32(const void* p) {
    uint32_t a;
    asm("{ .reg .u64 t; cvta.to.shared.u64 t, %1; cvt.u32.u64 %0, t; }"
        : "=r"(a) : "l"(p));
    return a;
}
__device__ __forceinline__ void cp16(uint32_t s, const void* g) {
    asm volatile("cp.async.cg.shared.global [%0], [%1], 16;" :: "r"(s), "l"(g));
}
#define CP_COMMIT() asm volatile("cp.async.commit_group;" ::: "memory")
#define CP_WAIT(n)  asm volatile("cp.async.wait_group %0;" :: "n"(n) : "memory")

__device__ __forceinline__ void ldsm4(uint32_t& r0, uint32_t& r1,
                                      uint32_t& r2, uint32_t& r3, uint32_t a) {
    asm volatile("ldmatrix.sync.aligned.m8n8.x4.shared.b16 {%0,%1,%2,%3}, [%4];"
                 : "=r"(r0), "=r"(r1), "=r"(r2), "=r"(r3) : "r"(a));
}
__device__ __forceinline__ void mma_f16(float* c, const uint32_t* a,
                                        uint32_t b0, uint32_t b1) {
    asm volatile(
        "mma.sync.aligned.m16n8k16.row.col.f32.f16.f16.f32 "
        "{%0,%1,%2,%3}, {%4,%5,%6,%7}, {%8,%9}, {%0,%1,%2,%3};"
        : "+f"(c[0]), "+f"(c[1]), "+f"(c[2]), "+f"(c[3])
        : "r"(a[0]), "r"(a[1]), "r"(a[2]), "r"(a[3]), "r"(b0), "r"(b1));
}

__device__ __forceinline__ void split_f16(float v, __half& h, __half& l) {
    h = __float2half(v);
    l = __float2half(v - __half2float(h));
}

// ============================================================================
// Converts
// ============================================================================
// Sh[n][k] = fp16(S[k][n])
__global__ __launch_bounds__(256) void convert_St(const float* __restrict__ S) {
    __shared__ float tile[64][65];
    int k0 = blockIdx.x * 64, n0 = blockIdx.y * 64;
    for (int idx = threadIdx.x; idx < 64 * 64; idx += 256) {
        int r = idx >> 6, c = idx & 63;
        tile[r][c] = S[(size_t)(k0 + r) * NN + n0 + c];
    }
    __syncthreads();
    for (int idx = threadIdx.x; idx < 64 * 64; idx += 256) {
        int r = idx >> 6, c = idx & 63;
        g_Sh[(size_t)(n0 + r) * NN + k0 + c] = __float2half(tile[c][r]);
    }
}
// Xh[b][d][k] = fp16(X[b][k][d])
__global__ __launch_bounds__(256) void convert_X(const float* __restrict__ X) {
    __shared__ float tile[64][65];
    int k0 = blockIdx.x * 64, b = blockIdx.y;
    for (int idx = threadIdx.x; idx < 64 * 64; idx += 256) {
        int r = idx >> 6, c = idx & 63;
        tile[r][c] = X[((size_t)b * NN + k0 + r) * BD + c];
    }
    __syncthreads();
    for (int idx = threadIdx.x; idx < 64 * 64; idx += 256) {
        int r = idx >> 6, c = idx & 63;
        g_Xh[((size_t)b * BD + r) * NN + k0 + c] = __float2half(tile[c][r]);
    }
}
// Ta = fp16split(W7)
__global__ __launch_bounds__(256) void convert_init(const float* __restrict__ W7) {
    size_t i = (size_t)blockIdx.x * 256 + threadIdx.x;
    __half h, l; split_f16(W7[i], h, l);
    g_Ta_h[i] = h; g_Ta_l[i] = l;
}

// ============================================================================
// GEMM core macros: tile 128x128, 256 thr (warps 2Mx4N, warp tile 64x32),
// BK=64, 3-stage cp.async ring. Stage = 256 rows x 144B = 36864 B.
// ============================================================================
#define STG_BYTES (256 * ROWB)
#define OP_SMEM   (3 * STG_BYTES)

#define LOAD_STAGE(Ap, Bp, k, slot)                                           \
    do {                                                                      \
        const uint32_t _base = sbase + (slot) * STG_BYTES;                    \
        _Pragma("unroll")                                                     \
        for (int _i = 0; _i < 8; ++_i) {                                      \
            int _idx = tid + _i * 256;                                        \
            int _r = _idx >> 3, _c = _idx & 7;                                \
            const void* _src = (_r < 128)                                     \
                ? (const void*)((Ap) + (size_t)(row0 + _r) * NN + (k) + _c * 8)   \
                : (const void*)((Bp) + (size_t)(col0 + _r - 128) * NN + (k) + _c * 8); \
            cp16(_base + _r * ROWB + _c * 16, _src);                          \
        }                                                                     \
        CP_COMMIT();                                                          \
    } while (0)

#define LDS_A(a, k16, sA)                                                     \
    _Pragma("unroll")                                                         \
    for (int _mt = 0; _mt < 4; ++_mt)                                         \
        ldsm4((a)[_mt][0], (a)[_mt][1], (a)[_mt][2], (a)[_mt][3],             \
              (sA) + (uint32_t)(wm + _mt * 16 + (lane & 15)) * ROWB           \
                   + (uint32_t)((k16) * 2 + (lane >> 4)) * 16)

#define LDS_B(b, k16, sB)                                                     \
    _Pragma("unroll")                                                         \
    for (int _p = 0; _p < 2; ++_p)                                            \
        ldsm4((b)[_p][0], (b)[_p][1], (b)[_p][2], (b)[_p][3],                 \
              (sB) + (uint32_t)(wn + _p * 16 + ((lane >> 4) << 3) + (lane & 7)) * ROWB \
                   + (uint32_t)((k16) * 2 + ((lane >> 3) & 1)) * 16)

#define MMA_ALL(acc, a, b)                                                    \
    _Pragma("unroll")                                                         \
    for (int _mt = 0; _mt < 4; ++_mt)                                         \
        _Pragma("unroll")                                                     \
        for (int _nt = 0; _nt < 4; ++_nt)                                     \
            mma_f16((acc)[_mt][_nt], (a)[_mt],                                \
                    (b)[_nt >> 1][(_nt & 1) * 2], (b)[_nt >> 1][(_nt & 1) * 2 + 1])

// ============================================================================
// gemm_splitk: partial[z] = (Th|Tl chunk) @ Sh over K-chunk z (512 of 2048)
// grid (8, 8, 4) = 256 CTAs, 256 threads.  8 stages per CTA.
// ============================================================================
__global__ __launch_bounds__(256, 2)
void gemm_splitk(int inSel) {
    extern __shared__ __align__(16) char smem[];
    const int tid  = threadIdx.x;
    const int lane = tid & 31, w = tid >> 5;
    const int wm   = (w >> 2) * 64;
    const int wn   = (w & 3) * 32;
    const int row0 = blockIdx.y * 128;
    const int col0 = blockIdx.x * 128;
    const int kb   = blockIdx.z * 512;
    const uint32_t sbase = smem_to_u32(smem);

    const __half* Ah = inSel ? g_Tb_h : g_Ta_h;
    const __half* Al = inSel ? g_Tb_l : g_Ta_l;

    auto issue = [&](int s, int slot) {
        const int kk = kb + s * 64;          // 0..2047
        const int k  = kk & 1023;
        const __half* Ap = (kk < 1024) ? Ah : Al;
        LOAD_STAGE(Ap, g_Sh, k, slot);
    };

    float acc[4][4][4] = {};
    issue(0, 0); issue(1, 1);

    for (int s = 0; s < 8; ++s) {
        CP_WAIT(1);
        __syncthreads();
        const uint32_t sA = sbase + (s % 3) * STG_BYTES;
        const uint32_t sB = sA + 128 * ROWB;

        uint32_t a[4][4], b[2][4];
        LDS_A(a, 0, sA); LDS_B(b, 0, sB);
        if (s + 2 < 8) issue(s + 2, (s + 2) % 3); else CP_COMMIT();
        MMA_ALL(acc, a, b);
        #pragma unroll
        for (int k16 = 1; k16 < 4; ++k16) {
            LDS_A(a, k16, sA); LDS_B(b, k16, sB);
            MMA_ALL(acc, a, b);
        }
    }

    float* P = g_part[blockIdx.z];
    const int g  = lane >> 2;
    const int i2 = (lane & 3) * 2;
    #pragma unroll
    for (int mt = 0; mt < 4; ++mt)
        #pragma unroll
        for (int nt = 0; nt < 4; ++nt) {
            const int m0 = row0 + wm + mt * 16 + g;
            const int n  = col0 + wn + nt * 8 + i2;
            *(float2*)(P + (size_t)m0 * NN + n)       = make_float2(acc[mt][nt][0], acc[mt][nt][1]);
            *(float2*)(P + (size_t)(m0 + 8) * NN + n) = make_float2(acc[mt][nt][2], acc[mt][nt][3]);
        }
}

// ============================================================================
// reduce_split: T_next = fp16split(sum(parts) + Wk)
//   lastStep != 0: skip writing the lo half (final GEMM reads hi only).
// ============================================================================
__global__ __launch_bounds__(256)
void reduce_split(const float* __restrict__ Wk, int inSel, int lastStep) {
    __half* Oh = inSel ? g_Ta_h : g_Tb_h;   // write opposite of input
    __half* Ol = inSel ? g_Ta_l : g_Tb_l;
    size_t i = ((size_t)blockIdx.x * 256 + threadIdx.x) * 4;
    float4 p0 = *(const float4*)&g_part[0][i];
    float4 p1 = *(const float4*)&g_part[1][i];
    float4 p2 = *(const float4*)&g_part[2][i];
    float4 p3 = *(const float4*)&g_part[3][i];
    float4 wv = *(const float4*)&Wk[i];
    float v0 = p0.x + p1.x + p2.x + p3.x + wv.x;
    float v1 = p0.y + p1.y + p2.y + p3.y + wv.y;
    float v2 = p0.z + p1.z + p2.z + p3.z + wv.z;
    float v3 = p0.w + p1.w + p2.w + p3.w + wv.w;
    __half h0, l0, h1, l1, h2, l2, h3, l3;
    split_f16(v0, h0, l0); split_f16(v1, h1, l1);
    split_f16(v2, h2, l2); split_f16(v3, h3, l3);
    *(__half2*)(Oh + i)     = __halves2half2(h0, h1);
    *(__half2*)(Oh + i + 2) = __halves2half2(h2, h3);
    if (!lastStep) {
        *(__half2*)(Ol + i)     = __halves2half2(l0, l1);
        *(__half2*)(Ol + i + 2) = __halves2half2(l2, l3);
    }
}

// ============================================================================
// gemm_final: out = Th @ Xh  — fp16 single-term, K = 1024 (16 stages).
// grid (64, 8) = 512 CTAs, 256 threads.
// ============================================================================
__global__ __launch_bounds__(256, 2)
void gemm_final(float* __restrict__ outp) {
    extern __shared__ __align__(16) char smem[];
    const int tid  = threadIdx.x;
    const int lane = tid & 31, w = tid >> 5;
    const int wm   = (w >> 2) * 64;
    const int wn   = (w & 3) * 32;
    const int row0 = blockIdx.y * 128;
    const int col0 = blockIdx.x * 128;     // global column in [0, 8192)
    const uint32_t sbase = smem_to_u32(smem);

    auto issue = [&](int s, int slot) {
        const int k = s * 64;              // 0..1023
        LOAD_STAGE(g_Tb_h, g_Xh, k, slot);
    };

    float acc[4][4][4] = {};
    issue(0, 0); issue(1, 1);

    for (int s = 0; s < 16; ++s) {
        CP_WAIT(1);
        __syncthreads();
        const uint32_t sA = sbase + (s % 3) * STG_BYTES;
        const uint32_t sB = sA + 128 * ROWB;

        uint32_t a[4][4], b[2][4];
        LDS_A(a, 0, sA); LDS_B(b, 0, sB);
        if (s + 2 < 16) issue(s + 2, (s + 2) % 3); else CP_COMMIT();
        MMA_ALL(acc, a, b);
        #pragma unroll
        for (int k16 = 1; k16 < 4; ++k16) {
            LDS_A(a, k16, sA); LDS_B(b, k16, sB);
            MMA_ALL(acc, a, b);
        }
    }

    const int g  = lane >> 2;
    const int i2 = (lane & 3) * 2;
    #pragma unroll
    for (int mt = 0; mt < 4; ++mt)
        #pragma unroll
        for (int nt = 0; nt < 4; ++nt) {
            const int m0    = row0 + wm + mt * 16 + g;
            const int ncolg = col0 + wn + nt * 8 + i2;
            const int batch = ncolg >> 6;
            const int d     = ncolg & 63;
            float* o0 = outp + ((size_t)batch * NN + m0) * BD + d;
            float* o1 = outp + ((size_t)batch * NN + m0 + 8) * BD + d;
            *(float2*)o0 = make_float2(acc[mt][nt][0], acc[mt][nt][1]);
            *(float2*)o1 = make_float2(acc[mt][nt][2], acc[mt][nt][3]);
        }
}

// ============================================================================
// Host orchestration (all-fp16):
//   T = W7; for k = 6..0: T = T @ fp16(S) + Wk  (2-term chain);
//   out = fp16(T) @ fp16(X)                     (1-term final)
// ============================================================================
extern "C" void kernel_launch(void* const* d_in, const int* in_sizes, int n_in,
                              void* d_out, int out_size) {
    const float* nodes  = (const float*)d_in[0];   // [128, 1024, 64]
    const float* weight = (const float*)d_in[1];   // [8, 1024, 1024]
    const float* S      = (const float*)d_in[2];   // [1024, 1024]
    float* out = (float*)d_out;                    // [128, 1024, 64]

    cudaFuncSetAttribute(gemm_splitk, cudaFuncAttributeMaxDynamicSharedMemorySize, OP_SMEM);
    cudaFuncSetAttribute(gemm_final,  cudaFuncAttributeMaxDynamicSharedMemorySize, OP_SMEM);

    convert_St  <<<dim3(16, 16), 256>>>(S);
    convert_X   <<<dim3(16, NB), 256>>>(nodes);
    convert_init<<<NN2 / 256, 256>>>(weight + (size_t)7 * NN2);

    for (int step = 0; step < 7; ++step) {
        int inSel = step & 1;  // 0: read Ta (write Tb), 1: read Tb (write Ta)
        gemm_splitk <<<dim3(8, 8, 4), 256, OP_SMEM>>>(inSel);
        reduce_split<<<NN2 / 1024, 256>>>(weight + (size_t)(6 - step) * NN2,
                                          inSel, step == 6 ? 1 : 0);
    }
    // 7 steps: final operator lands in Tb (hi only needed)
    gemm_final<<<dim3(64, 8), 256, OP_SMEM>>>(out);
}

// round 14
// speedup vs baseline: 1.6981x; 1.2992x over previous
#include <cuda_runtime.h>
#include <cuda_bf16.h>
#include <cuda_fp16.h>
#include <cstdint>

#define NN   1024
#define NN2  (NN * NN)
#define BD   64
#define NB   128
#define ROWB 144         // 128B k-data (BK=64) + 16B pad

// ============================================================================
// Device global scratch (allocation-free rule).  Single-fp16 pipeline:
//   T, S, X all fp16 (hi only); fp32 accumulation everywhere.
// ============================================================================
__device__ __align__(16) __half g_Sh[NN2];                         // S^T, fp16
__device__ __align__(16) __half g_Ta_h[NN2];
__device__ __align__(16) __half g_Tb_h[NN2];
__device__ __align__(16) __half g_Xh[(size_t)NB * BD * NN];        // X^T, fp16
__device__ __align__(16) float  g_part[2][NN2];

// ============================================================================
// PTX helpers (baseline sm_80-class, legal under compute_103)
// ============================================================================
__device__ __forceinline__ uint32_t smem_to_u32(const void* p) {
    uint32_t a;
    asm("{ .reg .u64 t; cvta.to.shared.u64 t, %1; cvt.u32.u64 %0, t; }"
        : "=r"(a) : "l"(p));
    return a;
}
__device__ __forceinline__ void cp16(uint32_t s, const void* g) {
    asm volatile("cp.async.cg.shared.global [%0], [%1], 16;" :: "r"(s), "l"(g));
}
#define CP_COMMIT() asm volatile("cp.async.commit_group;" ::: "memory")
#define CP_WAIT(n)  asm volatile("cp.async.wait_group %0;" :: "n"(n) : "memory")

__device__ __forceinline__ void ldsm4(uint32_t& r0, uint32_t& r1,
                                      uint32_t& r2, uint32_t& r3, uint32_t a) {
    asm volatile("ldmatrix.sync.aligned.m8n8.x4.shared.b16 {%0,%1,%2,%3}, [%4];"
                 : "=r"(r0), "=r"(r1), "=r"(r2), "=r"(r3) : "r"(a));
}
__device__ __forceinline__ void mma_f16(float* c, const uint32_t* a,
                                        uint32_t b0, uint32_t b1) {
    asm volatile(
        "mma.sync.aligned.m16n8k16.row.col.f32.f16.f16.f32 "
        "{%0,%1,%2,%3}, {%4,%5,%6,%7}, {%8,%9}, {%0,%1,%2,%3};"
        : "+f"(c[0]), "+f"(c[1]), "+f"(c[2]), "+f"(c[3])
        : "r"(a[0]), "r"(a[1]), "r"(a[2]), "r"(a[3]), "r"(b0), "r"(b1));
}

// ============================================================================
// Converts
// ============================================================================
// Sh[n][k] = fp16(S[k][n])
__global__ __launch_bounds__(256) void convert_St(const float* __restrict__ S) {
    __shared__ float tile[64][65];
    int k0 = blockIdx.x * 64, n0 = blockIdx.y * 64;
    for (int idx = threadIdx.x; idx < 64 * 64; idx += 256) {
        int r = idx >> 6, c = idx & 63;
        tile[r][c] = S[(size_t)(k0 + r) * NN + n0 + c];
    }
    __syncthreads();
    for (int idx = threadIdx.x; idx < 64 * 64; idx += 256) {
        int r = idx >> 6, c = idx & 63;
        g_Sh[(size_t)(n0 + r) * NN + k0 + c] = __float2half(tile[c][r]);
    }
}
// Xh[b][d][k] = fp16(X[b][k][d])
__global__ __launch_bounds__(256) void convert_X(const float* __restrict__ X) {
    __shared__ float tile[64][65];
    int k0 = blockIdx.x * 64, b = blockIdx.y;
    for (int idx = threadIdx.x; idx < 64 * 64; idx += 256) {
        int r = idx >> 6, c = idx & 63;
        tile[r][c] = X[((size_t)b * NN + k0 + r) * BD + c];
    }
    __syncthreads();
    for (int idx = threadIdx.x; idx < 64 * 64; idx += 256) {
        int r = idx >> 6, c = idx & 63;
        g_Xh[((size_t)b * BD + r) * NN + k0 + c] = __float2half(tile[c][r]);
    }
}
// Ta = fp16(W7)
__global__ __launch_bounds__(256) void convert_init(const float* __restrict__ W7) {
    size_t i = ((size_t)blockIdx.x * 256 + threadIdx.x) * 2;
    float2 v = *(const float2*)&W7[i];
    *(__half2*)(g_Ta_h + i) = __halves2half2(__float2half(v.x), __float2half(v.y));
}

// ============================================================================
// Fragment / stage macros
// ============================================================================
#define LDS_Am(a, M, k16, sA)                                                 \
    _Pragma("unroll")                                                         \
    for (int _mt = 0; _mt < (M); ++_mt)                                       \
        ldsm4((a)[_mt][0], (a)[_mt][1], (a)[_mt][2], (a)[_mt][3],             \
              (sA) + (uint32_t)(wm + _mt * 16 + (lane & 15)) * ROWB           \
                   + (uint32_t)((k16) * 2 + (lane >> 4)) * 16)

#define LDS_B(b, k16, sB)                                                     \
    _Pragma("unroll")                                                         \
    for (int _p = 0; _p < 2; ++_p)                                            \
        ldsm4((b)[_p][0], (b)[_p][1], (b)[_p][2], (b)[_p][3],                 \
              (sB) + (uint32_t)(wn + _p * 16 + ((lane >> 4) << 3) + (lane & 7)) * ROWB \
                   + (uint32_t)((k16) * 2 + ((lane >> 3) & 1)) * 16)

#define MMA_Mx4(acc, a, b, M)                                                 \
    _Pragma("unroll")                                                         \
    for (int _mt = 0; _mt < (M); ++_mt)                                       \
        _Pragma("unroll")                                                     \
        for (int _nt = 0; _nt < 4; ++_nt)                                     \
            mma_f16((acc)[_mt][_nt], (a)[_mt],                                \
                    (b)[_nt >> 1][(_nt & 1) * 2], (b)[_nt >> 1][(_nt & 1) * 2 + 1])

// ============================================================================
// gemm_splitk: partial[z] = Th(64 rows) @ Sh(128 cols) over K-chunk z (512)
// grid (8, 16, 2) = 256 CTAs, 256 thr (warps 2Mx4N, warp tile 32x32).
// 8 stages of BK=64; 3-stage ring. Stage = 192 rows x 144B = 27648 B.
// ============================================================================
#define SK_STG   (192 * ROWB)
#define SK_SMEM  (3 * SK_STG)

__global__ __launch_bounds__(256, 2)
void gemm_splitk(int inSel) {
    extern __shared__ __align__(16) char smem[];
    const int tid  = threadIdx.x;
    const int lane = tid & 31, w = tid >> 5;
    const int wm   = (w >> 2) * 32;       // 0, 32
    const int wn   = (w & 3) * 32;        // 0..96
    const int row0 = blockIdx.y * 64;
    const int col0 = blockIdx.x * 128;
    const int kb   = blockIdx.z * 512;
    const uint32_t sbase = smem_to_u32(smem);

    const __half* Ap = inSel ? g_Tb_h : g_Ta_h;

    auto issue = [&](int s, int slot) {
        const int k = kb + s * 64;
        const uint32_t base = sbase + slot * SK_STG;
        #pragma unroll
        for (int i = 0; i < 6; ++i) {
            int idx = tid + i * 256;           // 0..1535
            int r = idx >> 3, c = idx & 7;
            const __half* src = (r < 64)
                ? Ap   + (size_t)(row0 + r) * NN + k + c * 8
                : g_Sh + (size_t)(col0 + r - 64) * NN + k + c * 8;
            cp16(base + r * ROWB + c * 16, src);
        }
        CP_COMMIT();
    };

    float acc[2][4][4] = {};
    issue(0, 0); issue(1, 1);

    for (int s = 0; s < 8; ++s) {
        CP_WAIT(1);
        __syncthreads();
        const uint32_t sA = sbase + (s % 3) * SK_STG;
        const uint32_t sB = sA + 64 * ROWB;

        uint32_t a[2][4], b[2][4];
        LDS_Am(a, 2, 0, sA); LDS_B(b, 0, sB);
        if (s + 2 < 8) issue(s + 2, (s + 2) % 3); else CP_COMMIT();
        MMA_Mx4(acc, a, b, 2);
        #pragma unroll
        for (int k16 = 1; k16 < 4; ++k16) {
            LDS_Am(a, 2, k16, sA); LDS_B(b, k16, sB);
            MMA_Mx4(acc, a, b, 2);
        }
    }

    float* P = g_part[blockIdx.z];
    const int g  = lane >> 2;
    const int i2 = (lane & 3) * 2;
    #pragma unroll
    for (int mt = 0; mt < 2; ++mt)
        #pragma unroll
        for (int nt = 0; nt < 4; ++nt) {
            const int m0 = row0 + wm + mt * 16 + g;
            const int n  = col0 + wn + nt * 8 + i2;
            *(float2*)(P + (size_t)m0 * NN + n)       = make_float2(acc[mt][nt][0], acc[mt][nt][1]);
            *(float2*)(P + (size_t)(m0 + 8) * NN + n) = make_float2(acc[mt][nt][2], acc[mt][nt][3]);
        }
}

// ============================================================================
// reduce_split: T_next = fp16(part0 + part1 + Wk)
// ============================================================================
__global__ __launch_bounds__(256)
void reduce_split(const float* __restrict__ Wk, int inSel) {
    __half* Oh = inSel ? g_Ta_h : g_Tb_h;   // write opposite of input
    size_t i = ((size_t)blockIdx.x * 256 + threadIdx.x) * 4;
    float4 p0 = *(const float4*)&g_part[0][i];
    float4 p1 = *(const float4*)&g_part[1][i];
    float4 wv = *(const float4*)&Wk[i];
    float v0 = p0.x + p1.x + wv.x;
    float v1 = p0.y + p1.y + wv.y;
    float v2 = p0.z + p1.z + wv.z;
    float v3 = p0.w + p1.w + wv.w;
    *(__half2*)(Oh + i)     = __halves2half2(__float2half(v0), __float2half(v1));
    *(__half2*)(Oh + i + 2) = __halves2half2(__float2half(v2), __float2half(v3));
}

// ============================================================================
// gemm_final: out = Th @ Xh  — fp16, K = 1024 (16 stages).
// grid (64, 8) = 512 CTAs, 256 thr (warps 2Mx4N, warp tile 64x32).
// Stage = 256 rows x 144B = 36864 B.
// ============================================================================
#define F_STG   (256 * ROWB)
#define F_SMEM  (3 * F_STG)

__global__ __launch_bounds__(256, 2)
void gemm_final(float* __restrict__ outp) {
    extern __shared__ __align__(16) char smem[];
    const int tid  = threadIdx.x;
    const int lane = tid & 31, w = tid >> 5;
    const int wm   = (w >> 2) * 64;
    const int wn   = (w & 3) * 32;
    const int row0 = blockIdx.y * 128;
    const int col0 = blockIdx.x * 128;     // global column in [0, 8192)
    const uint32_t sbase = smem_to_u32(smem);

    auto issue = [&](int s, int slot) {
        const int k = s * 64;              // 0..1023
        const uint32_t base = sbase + slot * F_STG;
        #pragma unroll
        for (int i = 0; i < 8; ++i) {
            int idx = tid + i * 256;           // 0..2047
            int r = idx >> 3, c = idx & 7;
            const __half* src = (r < 128)
                ? g_Tb_h + (size_t)(row0 + r) * NN + k + c * 8
                : g_Xh   + (size_t)(col0 + r - 128) * NN + k + c * 8;
            cp16(base + r * ROWB + c * 16, src);
        }
        CP_COMMIT();
    };

    float acc[4][4][4] = {};
    issue(0, 0); issue(1, 1);

    for (int s = 0; s < 16; ++s) {
        CP_WAIT(1);
        __syncthreads();
        const uint32_t sA = sbase + (s % 3) * F_STG;
        const uint32_t sB = sA + 128 * ROWB;

        uint32_t a[4][4], b[2][4];
        LDS_Am(a, 4, 0, sA); LDS_B(b, 0, sB);
        if (s + 2 < 16) issue(s + 2, (s + 2) % 3); else CP_COMMIT();
        MMA_Mx4(acc, a, b, 4);
        #pragma unroll
        for (int k16 = 1; k16 < 4; ++k16) {
            LDS_Am(a, 4, k16, sA); LDS_B(b, k16, sB);
            MMA_Mx4(acc, a, b, 4);
        }
    }

    const int g  = lane >> 2;
    const int i2 = (lane & 3) * 2;
    #pragma unroll
    for (int mt = 0; mt < 4; ++mt)
        #pragma unroll
        for (int nt = 0; nt < 4; ++nt) {
            const int m0    = row0 + wm + mt * 16 + g;
            const int ncolg = col0 + wn + nt * 8 + i2;
            const int batch = ncolg >> 6;
            const int d     = ncolg & 63;
            float* o0 = outp + ((size_t)batch * NN + m0) * BD + d;
            float* o1 = outp + ((size_t)batch * NN + m0 + 8) * BD + d;
            *(float2*)o0 = make_float2(acc[mt][nt][0], acc[mt][nt][1]);
            *(float2*)o1 = make_float2(acc[mt][nt][2], acc[mt][nt][3]);
        }
}

// ============================================================================
// Host orchestration (single-fp16 pipeline):
//   T = fp16(W7); for k = 6..0: T = fp16(T) @ fp16(S) + Wk;  out = T @ fp16(X)
// ============================================================================
extern "C" void kernel_launch(void* const* d_in, const int* in_sizes, int n_in,
                              void* d_out, int out_size) {
    const float* nodes  = (const float*)d_in[0];   // [128, 1024, 64]
    const float* weight = (const float*)d_in[1];   // [8, 1024, 1024]
    const float* S      = (const float*)d_in[2];   // [1024, 1024]
    float* out = (float*)d_out;                    // [128, 1024, 64]

    cudaFuncSetAttribute(gemm_splitk, cudaFuncAttributeMaxDynamicSharedMemorySize, SK_SMEM);
    cudaFuncSetAttribute(gemm_final,  cudaFuncAttributeMaxDynamicSharedMemorySize, F_SMEM);

    convert_St  <<<dim3(16, 16), 256>>>(S);
    convert_X   <<<dim3(16, NB), 256>>>(nodes);
    convert_init<<<NN2 / 512, 256>>>(weight + (size_t)7 * NN2);

    for (int step = 0; step < 7; ++step) {
        int inSel = step & 1;  // 0: read Ta (write Tb), 1: read Tb (write Ta)
        gemm_splitk <<<dim3(8, 16, 2), 256, SK_SMEM>>>(inSel);
        reduce_split<<<NN2 / 1024, 256>>>(weight + (size_t)(6 - step) * NN2, inSel);
    }
    // 7 steps: final operator lands in Tb
    gemm_final<<<dim3(64, 8), 256, F_SMEM>>>(out);
}

// round 15
// speedup vs baseline: 1.7344x; 1.0214x over previous
#include <cuda_runtime.h>
#include <cuda_bf16.h>
#include <cuda_fp16.h>
#include <cstdint>

#define NN   1024
#define NN2  (NN * NN)
#define BD   64
#define NB   128
#define ROWB 144         // 128B k-data (BK=64) + 16B pad

// ============================================================================
// Device global scratch (allocation-free rule).  Single-fp16 pipeline:
//   T, S, X all fp16; fp32 accumulation everywhere.
// ============================================================================
__device__ __align__(16) __half g_Sh[NN2];                         // S^T, fp16
__device__ __align__(16) __half g_Ta_h[NN2];
__device__ __align__(16) __half g_Tb_h[NN2];
__device__ __align__(16) __half g_Xh[(size_t)NB * BD * NN];        // X^T, fp16

// ============================================================================
// PTX helpers (baseline sm_80-class, legal under compute_103)
// ============================================================================
__device__ __forceinline__ uint32_t smem_to_u32(const void* p) {
    uint32_t a;
    asm("{ .reg .u64 t; cvta.to.shared.u64 t, %1; cvt.u32.u64 %0, t; }"
        : "=r"(a) : "l"(p));
    return a;
}
__device__ __forceinline__ void cp16(uint32_t s, const void* g) {
    asm volatile("cp.async.cg.shared.global [%0], [%1], 16;" :: "r"(s), "l"(g));
}
#define CP_COMMIT() asm volatile("cp.async.commit_group;" ::: "memory")
#define CP_WAIT(n)  asm volatile("cp.async.wait_group %0;" :: "n"(n) : "memory")

__device__ __forceinline__ void ldsm4(uint32_t& r0, uint32_t& r1,
                                      uint32_t& r2, uint32_t& r3, uint32_t a) {
    asm volatile("ldmatrix.sync.aligned.m8n8.x4.shared.b16 {%0,%1,%2,%3}, [%4];"
                 : "=r"(r0), "=r"(r1), "=r"(r2), "=r"(r3) : "r"(a));
}
__device__ __forceinline__ void mma_f16(float* c, const uint32_t* a,
                                        uint32_t b0, uint32_t b1) {
    asm volatile(
        "mma.sync.aligned.m16n8k16.row.col.f32.f16.f16.f32 "
        "{%0,%1,%2,%3}, {%4,%5,%6,%7}, {%8,%9}, {%0,%1,%2,%3};"
        : "+f"(c[0]), "+f"(c[1]), "+f"(c[2]), "+f"(c[3])
        : "r"(a[0]), "r"(a[1]), "r"(a[2]), "r"(a[3]), "r"(b0), "r"(b1));
}

// ============================================================================
// Converts
// ============================================================================
// Sh[n][k] = fp16(S[k][n])
__global__ __launch_bounds__(256) void convert_St(const float* __restrict__ S) {
    __shared__ float tile[64][65];
    int k0 = blockIdx.x * 64, n0 = blockIdx.y * 64;
    for (int idx = threadIdx.x; idx < 64 * 64; idx += 256) {
        int r = idx >> 6, c = idx & 63;
        tile[r][c] = S[(size_t)(k0 + r) * NN + n0 + c];
    }
    __syncthreads();
    for (int idx = threadIdx.x; idx < 64 * 64; idx += 256) {
        int r = idx >> 6, c = idx & 63;
        g_Sh[(size_t)(n0 + r) * NN + k0 + c] = __float2half(tile[c][r]);
    }
}
// Xh[b][d][k] = fp16(X[b][k][d])
__global__ __launch_bounds__(256) void convert_X(const float* __restrict__ X) {
    __shared__ float tile[64][65];
    int k0 = blockIdx.x * 64, b = blockIdx.y;
    for (int idx = threadIdx.x; idx < 64 * 64; idx += 256) {
        int r = idx >> 6, c = idx & 63;
        tile[r][c] = X[((size_t)b * NN + k0 + r) * BD + c];
    }
    __syncthreads();
    for (int idx = threadIdx.x; idx < 64 * 64; idx += 256) {
        int r = idx >> 6, c = idx & 63;
        g_Xh[((size_t)b * BD + r) * NN + k0 + c] = __float2half(tile[c][r]);
    }
}
// Ta = fp16(W7)
__global__ __launch_bounds__(256) void convert_init(const float* __restrict__ W7) {
    size_t i = ((size_t)blockIdx.x * 256 + threadIdx.x) * 2;
    float2 v = *(const float2*)&W7[i];
    *(__half2*)(g_Ta_h + i) = __halves2half2(__float2half(v.x), __float2half(v.y));
}

// ============================================================================
// Fragment / MMA macros
// ============================================================================
#define LDS_Am(a, M, k16, sA)                                                 \
    _Pragma("unroll")                                                         \
    for (int _mt = 0; _mt < (M); ++_mt)                                       \
        ldsm4((a)[_mt][0], (a)[_mt][1], (a)[_mt][2], (a)[_mt][3],             \
              (sA) + (uint32_t)(wm + _mt * 16 + (lane & 15)) * ROWB           \
                   + (uint32_t)((k16) * 2 + (lane >> 4)) * 16)

#define LDS_B(b, k16, sB)                                                     \
    _Pragma("unroll")                                                         \
    for (int _p = 0; _p < 2; ++_p)                                            \
        ldsm4((b)[_p][0], (b)[_p][1], (b)[_p][2], (b)[_p][3],                 \
              (sB) + (uint32_t)(wn + _p * 16 + ((lane >> 4) << 3) + (lane & 7)) * ROWB \
                   + (uint32_t)((k16) * 2 + ((lane >> 3) & 1)) * 16)

#define MMA_Mx4(acc, a, b, M)                                                 \
    _Pragma("unroll")                                                         \
    for (int _mt = 0; _mt < (M); ++_mt)                                       \
        _Pragma("unroll")                                                     \
        for (int _nt = 0; _nt < 4; ++_nt)                                     \
            mma_f16((acc)[_mt][_nt], (a)[_mt],                                \
                    (b)[_nt >> 1][(_nt & 1) * 2], (b)[_nt >> 1][(_nt & 1) * 2 + 1])

// ============================================================================
// gemm_step: T_next(64x64 tile) = fp16( T @ Sh + Wk )  over K = 1024.
// grid (16, 16) = 256 CTAs, 128 thr (warps 2Mx2N, warp tile 32x32).
// 16 stages of BK=64; 3-stage ring. Stage = 128 rows x 144B = 18432 B.
// No split-K, no reduce kernel: Wk-add + fp16 store fused in epilogue.
// ============================================================================
#define ST_STG   (128 * ROWB)
#define ST_SMEM  (3 * ST_STG)

__global__ __launch_bounds__(128, 3)
void gemm_step(int inSel, const float* __restrict__ Wk) {
    extern __shared__ __align__(16) char smem[];
    const int tid  = threadIdx.x;
    const int lane = tid & 31, w = tid >> 5;
    const int wm   = (w >> 1) * 32;       // 0, 32
    const int wn   = (w & 1) * 32;        // 0, 32
    const int row0 = blockIdx.y * 64;
    const int col0 = blockIdx.x * 64;
    const uint32_t sbase = smem_to_u32(smem);

    const __half* Ap = inSel ? g_Tb_h : g_Ta_h;
    __half*       Oh = inSel ? g_Ta_h : g_Tb_h;

    auto issue = [&](int s, int slot) {
        const int k = s * 64;
        const uint32_t base = sbase + slot * ST_STG;
        #pragma unroll
        for (int i = 0; i < 8; ++i) {
            int idx = tid + i * 128;           // 0..1023
            int r = idx >> 3, c = idx & 7;
            const __half* src = (r < 64)
                ? Ap   + (size_t)(row0 + r) * NN + k + c * 8
                : g_Sh + (size_t)(col0 + r - 64) * NN + k + c * 8;
            cp16(base + r * ROWB + c * 16, src);
        }
        CP_COMMIT();
    };

    float acc[2][4][4] = {};
    issue(0, 0); issue(1, 1);

    for (int s = 0; s < 16; ++s) {
        CP_WAIT(1);
        __syncthreads();
        const uint32_t sA = sbase + (s % 3) * ST_STG;
        const uint32_t sB = sA + 64 * ROWB;

        uint32_t a[2][4], b[2][4];
        LDS_Am(a, 2, 0, sA); LDS_B(b, 0, sB);
        if (s + 2 < 16) issue(s + 2, (s + 2) % 3); else CP_COMMIT();
        MMA_Mx4(acc, a, b, 2);
        #pragma unroll
        for (int k16 = 1; k16 < 4; ++k16) {
            LDS_Am(a, 2, k16, sA); LDS_B(b, k16, sB);
            MMA_Mx4(acc, a, b, 2);
        }
    }

    // epilogue: + Wk (fp32), convert fp16, store T_next
    const int g  = lane >> 2;
    const int i2 = (lane & 3) * 2;
    #pragma unroll
    for (int mt = 0; mt < 2; ++mt)
        #pragma unroll
        for (int nt = 0; nt < 4; ++nt) {
            const int m0 = row0 + wm + mt * 16 + g;
            const int n  = col0 + wn + nt * 8 + i2;
            float2 w0 = *(const float2*)(Wk + (size_t)m0 * NN + n);
            float2 w1 = *(const float2*)(Wk + (size_t)(m0 + 8) * NN + n);
            *(__half2*)(Oh + (size_t)m0 * NN + n) =
                __halves2half2(__float2half(acc[mt][nt][0] + w0.x),
                               __float2half(acc[mt][nt][1] + w0.y));
            *(__half2*)(Oh + (size_t)(m0 + 8) * NN + n) =
                __halves2half2(__float2half(acc[mt][nt][2] + w1.x),
                               __float2half(acc[mt][nt][3] + w1.y));
        }
}

// ============================================================================
// gemm_final: out = Th @ Xh  — fp16, K = 1024 (16 stages).
// grid (64, 8) = 512 CTAs, 256 thr (warps 2Mx4N, warp tile 64x32).
// Stage = 256 rows x 144B = 36864 B.
// ============================================================================
#define F_STG   (256 * ROWB)
#define F_SMEM  (3 * F_STG)

__global__ __launch_bounds__(256, 2)
void gemm_final(float* __restrict__ outp) {
    extern __shared__ __align__(16) char smem[];
    const int tid  = threadIdx.x;
    const int lane = tid & 31, w = tid >> 5;
    const int wm   = (w >> 2) * 64;
    const int wn   = (w & 3) * 32;
    const int row0 = blockIdx.y * 128;
    const int col0 = blockIdx.x * 128;     // global column in [0, 8192)
    const uint32_t sbase = smem_to_u32(smem);

    auto issue = [&](int s, int slot) {
        const int k = s * 64;              // 0..1023
        const uint32_t base = sbase + slot * F_STG;
        #pragma unroll
        for (int i = 0; i < 8; ++i) {
            int idx = tid + i * 256;           // 0..2047
            int r = idx >> 3, c = idx & 7;
            const __half* src = (r < 128)
                ? g_Tb_h + (size_t)(row0 + r) * NN + k + c * 8
                : g_Xh   + (size_t)(col0 + r - 128) * NN + k + c * 8;
            cp16(base + r * ROWB + c * 16, src);
        }
        CP_COMMIT();
    };

    float acc[4][4][4] = {};
    issue(0, 0); issue(1, 1);

    for (int s = 0; s < 16; ++s) {
        CP_WAIT(1);
        __syncthreads();
        const uint32_t sA = sbase + (s % 3) * F_STG;
        const uint32_t sB = sA + 128 * ROWB;

        uint32_t a[4][4], b[2][4];
        LDS_Am(a, 4, 0, sA); LDS_B(b, 0, sB);
        if (s + 2 < 16) issue(s + 2, (s + 2) % 3); else CP_COMMIT();
        MMA_Mx4(acc, a, b, 4);
        #pragma unroll
        for (int k16 = 1; k16 < 4; ++k16) {
            LDS_Am(a, 4, k16, sA); LDS_B(b, k16, sB);
            MMA_Mx4(acc, a, b, 4);
        }
    }

    const int g  = lane >> 2;
    const int i2 = (lane & 3) * 2;
    #pragma unroll
    for (int mt = 0; mt < 4; ++mt)
        #pragma unroll
        for (int nt = 0; nt < 4; ++nt) {
            const int m0    = row0 + wm + mt * 16 + g;
            const int ncolg = col0 + wn + nt * 8 + i2;
            const int batch = ncolg >> 6;
            const int d     = ncolg & 63;
            float* o0 = outp + ((size_t)batch * NN + m0) * BD + d;
            float* o1 = outp + ((size_t)batch * NN + m0 + 8) * BD + d;
            *(float2*)o0 = make_float2(acc[mt][nt][0], acc[mt][nt][1]);
            *(float2*)o1 = make_float2(acc[mt][nt][2], acc[mt][nt][3]);
        }
}

// ============================================================================
// Host orchestration (single-fp16 pipeline, fused step epilogue):
//   T = fp16(W7); for k = 6..0: T = fp16(T @ S + Wk);  out = T @ fp16(X)
// ============================================================================
extern "C" void kernel_launch(void* const* d_in, const int* in_sizes, int n_in,
                              void* d_out, int out_size) {
    const float* nodes  = (const float*)d_in[0];   // [128, 1024, 64]
    const float* weight = (const float*)d_in[1];   // [8, 1024, 1024]
    const float* S      = (const float*)d_in[2];   // [1024, 1024]
    float* out = (float*)d_out;                    // [128, 1024, 64]

    cudaFuncSetAttribute(gemm_step,  cudaFuncAttributeMaxDynamicSharedMemorySize, ST_SMEM);
    cudaFuncSetAttribute(gemm_final, cudaFuncAttributeMaxDynamicSharedMemorySize, F_SMEM);

    convert_St  <<<dim3(16, 16), 256>>>(S);
    convert_X   <<<dim3(16, NB), 256>>>(nodes);
    convert_init<<<NN2 / 512, 256>>>(weight + (size_t)7 * NN2);

    for (int step = 0; step < 7; ++step) {
        int inSel = step & 1;  // 0: read Ta (write Tb), 1: read Tb (write Ta)
        gemm_step<<<dim3(16, 16), 128, ST_SMEM>>>(
            inSel, weight + (size_t)(6 - step) * NN2);
    }
    // 7 steps: final operator lands in Tb
    gemm_final<<<dim3(64, 8), 256, F_SMEM>>>(out);
}